// round 4
// baseline (speedup 1.0000x reference)
#include <cuda_runtime.h>
#include <cstdint>

#define Bn 64
#define Fn 64
#define Cn 8
#define Sn 128
#define Pn (Sn * Sn)          // 16384 pixels per image
#define Kn 10                 // steps_to_run
#define BP (Bn * Pn)          // 1048576 total pixels
#define PB 64                 // partial blocks per batch (16384/256)
#define NBLK (Bn * PB)        // 4096 step/partial blocks

// Scratch (device globals: allocation-free per harness rules)
__device__ float g_colour[(size_t)Bn * Cn * Pn];  // [b][c][p]   33.5 MB
__device__ float g_logs[(size_t)BP];              // [b][p]       4 MB
__device__ float g_stage[(size_t)(Kn - 1) * BP];  // [k][b*p]    37.7 MB
__device__ float g_seed[Bn * Cn];                 // [b][c]
__device__ float g_pval[NBLK];
__device__ int   g_pidx[NBLK];
__device__ float g_invsig;                        // 1/sigma

// ---------------------------------------------------------------------------
// Block-level argmax reduce (first-index tie-break), blockDim=256.
// ---------------------------------------------------------------------------
__device__ __forceinline__ void block_argmax_256(float v, int p, int blk) {
#pragma unroll
    for (int o = 16; o; o >>= 1) {
        float ov = __shfl_down_sync(0xFFFFFFFFu, v, o);
        int   op = __shfl_down_sync(0xFFFFFFFFu, p, o);
        if (ov > v || (ov == v && op < p)) { v = ov; p = op; }
    }
    __shared__ float sv[8];
    __shared__ int   sp[8];
    int tid = threadIdx.x;
    int wid = tid >> 5;
    if ((tid & 31) == 0) { sv[wid] = v; sp[wid] = p; }
    __syncthreads();
    if (tid == 0) {
#pragma unroll
        for (int i = 1; i < 8; i++)
            if (sv[i] > v || (sv[i] == v && sp[i] < p)) { v = sv[i]; p = sp[i]; }
        g_pval[blk] = v;
        g_pidx[blk] = p;
    }
}

// ---------------------------------------------------------------------------
// Kernel 1: 1x1 conv + gate + coordinate channels -> g_colour.
// ---------------------------------------------------------------------------
__global__ void conv_kernel(const float4* __restrict__ feat,
                            const float* __restrict__ w,
                            const float* __restrict__ bias,
                            const float* __restrict__ gate) {
    __shared__ float ws[Cn * Fn];
    __shared__ float bs[Cn];
    int tid = threadIdx.x;
    for (int i = tid; i < Cn * Fn; i += blockDim.x) ws[i] = w[i];
    if (tid < Cn) bs[tid] = bias[tid];
    __syncthreads();

    int gidx = blockIdx.x * blockDim.x + tid;   // 0 .. BP/4-1
    int b = gidx >> 12;
    int q = gidx & 4095;

    const float4* fb = feat + (size_t)b * (Fn * Pn / 4) + q;

    float4 acc[Cn];
#pragma unroll
    for (int c = 0; c < Cn; c++) {
        float bb = bs[c];
        acc[c] = make_float4(bb, bb, bb, bb);
    }

#pragma unroll 8
    for (int f = 0; f < Fn; f++) {
        float4 v = __ldcs(&fb[(size_t)f * (Pn / 4)]);   // stream features
#pragma unroll
        for (int c = 0; c < Cn; c++) {
            float wc = ws[c * Fn + f];
            acc[c].x += v.x * wc;
            acc[c].y += v.y * wc;
            acc[c].z += v.z * wc;
            acc[c].w += v.w * wc;
        }
    }

    float g = gate[0];
#pragma unroll
    for (int c = 0; c < Cn; c++) {
        acc[c].x *= g; acc[c].y *= g; acc[c].z *= g; acc[c].w *= g;
    }

    int p0 = q << 2;
    int h  = p0 >> 7;
    int wc0 = p0 & 127;
    const float step = 2.0f / 127.0f;
    float yy = -1.0f + step * (float)h;
    acc[6].x += yy; acc[6].y += yy; acc[6].z += yy; acc[6].w += yy;
    float xx = -1.0f + step * (float)wc0;
    acc[7].x += xx;
    acc[7].y += xx + step;
    acc[7].z += xx + 2.0f * step;
    acc[7].w += xx + 3.0f * step;

    float4* cb = (float4*)g_colour;
#pragma unroll
    for (int c = 0; c < Cn; c++)
        cb[((size_t)b * Cn + c) * (Pn / 4) + q] = acc[c];
}

// ---------------------------------------------------------------------------
// Kernel 2: initial argmax partials over rand_pixel; precompute 1/sigma.
// ---------------------------------------------------------------------------
__global__ void init_partial_kernel(const float* __restrict__ rp,
                                    const float* __restrict__ log_sigma) {
    int idx = blockIdx.x * blockDim.x + threadIdx.x;
    if (idx == 0) g_invsig = expf(-log_sigma[0]);
    int p = idx & (Pn - 1);
    block_argmax_256(rp[idx], p, blockIdx.x);
}

// ---------------------------------------------------------------------------
// Kernel 3: final argmax reduce per batch + seed gather. 64 blocks x 64 thr.
// ---------------------------------------------------------------------------
__global__ void reduce_seed_kernel() {
    int b = blockIdx.x;
    int tid = threadIdx.x;
    float v = g_pval[b * PB + tid];
    int   p = g_pidx[b * PB + tid];
    int blk = tid;
#pragma unroll
    for (int o = 16; o; o >>= 1) {
        float ov = __shfl_down_sync(0xFFFFFFFFu, v, o);
        int   op = __shfl_down_sync(0xFFFFFFFFu, p, o);
        int   ob = __shfl_down_sync(0xFFFFFFFFu, blk, o);
        if (ov > v || (ov == v && ob < blk)) { v = ov; p = op; blk = ob; }
    }
    __shared__ float sv[2];
    __shared__ int   sp[2];
    __shared__ int   sb[2];
    if ((tid & 31) == 0) { sv[tid >> 5] = v; sp[tid >> 5] = p; sb[tid >> 5] = blk; }
    __syncthreads();
    if (tid == 0) {
        if (sv[1] > v || (sv[1] == v && sb[1] < blk)) { v = sv[1]; p = sp[1]; }
#pragma unroll
        for (int c = 0; c < Cn; c++)
            g_seed[b * Cn + c] = g_colour[((size_t)b * Cn + c) * Pn + p];
    }
}

// ---------------------------------------------------------------------------
// Kernel 4: mask step + fused next-step argmax partial.
//   k<Kn-1: stage[k][idx] = log_m ; logs update ; argmax partial
//   k=Kn-1: compute log_m(9) and final scope, read stage, write out [idx][11]
// ---------------------------------------------------------------------------
__global__ void step_kernel(float* __restrict__ out,
                            const float* __restrict__ rp,
                            int k, int first, int last) {
    int idx = blockIdx.x * blockDim.x + threadIdx.x;  // 0 .. BP-1
    int b = idx >> 14;
    int p = idx & (Pn - 1);

    float seed[Cn];
#pragma unroll
    for (int c = 0; c < Cn; c++) seed[c] = __ldg(&g_seed[b * Cn + c]);

    float ls = first ? 0.0f : g_logs[idx];

    const float* cb = g_colour + (size_t)b * Cn * Pn + p;
    float d2 = 0.0f;
#pragma unroll
    for (int c = 0; c < Cn; c++) {
        float t = __ldg(cb + (size_t)c * Pn) - seed[c];
        d2 += t * t;
    }

    const float LOG2E = 1.4426950408889634f;
    const float L_LO  = -4.6051702f;      // log(0.01f)
    const float L_HI  = -0.010050326f;    // log(0.99f)

    float invsig = g_invsig;
    float t = -(d2 * invsig);                      // ln-scale exponent
    float alpha = exp2f(t * LOG2E);
    alpha = fminf(fmaxf(alpha, 0.01f), 0.99f);
    float log_a = fminf(fmaxf(t, L_LO), L_HI);     // == log(clamped alpha)
    float log_m = ls + log_a;
    float ls_new = ls + logf(1.0f - alpha);

    if (!last) {
        g_stage[(size_t)k * BP + idx] = log_m;
        g_logs[idx] = ls_new;
        float v = rp[idx] * expf(ls_new);
        block_argmax_256(v, p, blockIdx.x);
    } else {
        // gather staged masks + final two values; contiguous 44B store
        float* op = out + (size_t)idx * (Kn + 1);
#pragma unroll
        for (int j = 0; j < Kn - 1; j++)
            __stcs(&op[j], __ldcs(&g_stage[(size_t)j * BP + idx]));
        __stcs(&op[Kn - 1], log_m);
        __stcs(&op[Kn], ls_new);
    }
}

// ---------------------------------------------------------------------------
extern "C" void kernel_launch(void* const* d_in, const int* in_sizes, int n_in,
                              void* d_out, int out_size) {
    const float* features  = (const float*)d_in[0];
    const float* rand_pix  = (const float*)d_in[1];
    const float* conv_w    = (const float*)d_in[2];
    const float* conv_b    = (const float*)d_in[3];
    const float* gate      = (const float*)d_in[4];
    const float* log_sigma = (const float*)d_in[5];
    float* out = (float*)d_out;

    (void)in_sizes; (void)n_in; (void)out_size;

    conv_kernel<<<(BP / 4) / 256, 256>>>((const float4*)features,
                                         conv_w, conv_b, gate);
    init_partial_kernel<<<NBLK, 256>>>(rand_pix, log_sigma);

    for (int k = 0; k < Kn; k++) {
        reduce_seed_kernel<<<Bn, PB>>>();
        step_kernel<<<NBLK, 256>>>(out, rand_pix,
                                   k, k == 0 ? 1 : 0, k == Kn - 1 ? 1 : 0);
    }
}

// round 6
// speedup vs baseline: 1.1008x; 1.1008x over previous
#include <cuda_runtime.h>
#include <cstdint>

#define Bn 64
#define Fn 64
#define Cn 8
#define Sn 128
#define Pn (Sn * Sn)          // 16384 pixels per image
#define Kn 10                 // steps_to_run
#define BP (Bn * Pn)          // 1048576 total pixels
#define PB 64                 // partial blocks per batch (16384/256)
#define NBLK (Bn * PB)        // 4096 step/partial blocks

// Scratch (device globals: allocation-free per harness rules)
__device__ float g_colour[(size_t)Bn * Cn * Pn];  // [b][c][p]   33.5 MB
__device__ float g_logs[(size_t)BP];              // [b][p]       4 MB
__device__ float g_stage[(size_t)(Kn - 1) * BP];  // [k][b*p]    37.7 MB (streamed)
__device__ float g_pval[NBLK];
__device__ int   g_pidx[NBLK];
__device__ float g_invsig;                        // 1/sigma

// ---------------------------------------------------------------------------
// Block-level argmax partial reduce (first-index tie-break), blockDim=256.
// ---------------------------------------------------------------------------
__device__ __forceinline__ void block_argmax_256(float v, int p, int blk) {
#pragma unroll
    for (int o = 16; o; o >>= 1) {
        float ov = __shfl_down_sync(0xFFFFFFFFu, v, o);
        int   op = __shfl_down_sync(0xFFFFFFFFu, p, o);
        if (ov > v || (ov == v && op < p)) { v = ov; p = op; }
    }
    __shared__ float sv[8];
    __shared__ int   sp[8];
    int tid = threadIdx.x;
    int wid = tid >> 5;
    if ((tid & 31) == 0) { sv[wid] = v; sp[wid] = p; }
    __syncthreads();
    if (tid == 0) {
#pragma unroll
        for (int i = 1; i < 8; i++)
            if (sv[i] > v || (sv[i] == v && sp[i] < p)) { v = sv[i]; p = sp[i]; }
        g_pval[blk] = v;
        g_pidx[blk] = p;
    }
}

// ---------------------------------------------------------------------------
// Kernel 1: 1x1 conv + gate + coordinate channels -> g_colour.
// ---------------------------------------------------------------------------
__global__ void conv_kernel(const float4* __restrict__ feat,
                            const float* __restrict__ w,
                            const float* __restrict__ bias,
                            const float* __restrict__ gate) {
    __shared__ float ws[Cn * Fn];
    __shared__ float bs[Cn];
    int tid = threadIdx.x;
    for (int i = tid; i < Cn * Fn; i += blockDim.x) ws[i] = w[i];
    if (tid < Cn) bs[tid] = bias[tid];
    __syncthreads();

    int gidx = blockIdx.x * blockDim.x + tid;   // 0 .. BP/4-1
    int b = gidx >> 12;
    int q = gidx & 4095;

    const float4* fb = feat + (size_t)b * (Fn * Pn / 4) + q;

    float4 acc[Cn];
#pragma unroll
    for (int c = 0; c < Cn; c++) {
        float bb = bs[c];
        acc[c] = make_float4(bb, bb, bb, bb);
    }

#pragma unroll 8
    for (int f = 0; f < Fn; f++) {
        float4 v = __ldcs(&fb[(size_t)f * (Pn / 4)]);   // stream features
#pragma unroll
        for (int c = 0; c < Cn; c++) {
            float wc = ws[c * Fn + f];
            acc[c].x += v.x * wc;
            acc[c].y += v.y * wc;
            acc[c].z += v.z * wc;
            acc[c].w += v.w * wc;
        }
    }

    float g = gate[0];
#pragma unroll
    for (int c = 0; c < Cn; c++) {
        acc[c].x *= g; acc[c].y *= g; acc[c].z *= g; acc[c].w *= g;
    }

    int p0 = q << 2;
    int h  = p0 >> 7;
    int wc0 = p0 & 127;
    const float step = 2.0f / 127.0f;
    float yy = -1.0f + step * (float)h;
    acc[6].x += yy; acc[6].y += yy; acc[6].z += yy; acc[6].w += yy;
    float xx = -1.0f + step * (float)wc0;
    acc[7].x += xx;
    acc[7].y += xx + step;
    acc[7].z += xx + 2.0f * step;
    acc[7].w += xx + 3.0f * step;

    float4* cb = (float4*)g_colour;
#pragma unroll
    for (int c = 0; c < Cn; c++)
        cb[((size_t)b * Cn + c) * (Pn / 4) + q] = acc[c];
}

// ---------------------------------------------------------------------------
// Kernel 2: initial argmax partials over rand_pixel; precompute 1/sigma.
// ---------------------------------------------------------------------------
__global__ void init_partial_kernel(const float* __restrict__ rp,
                                    const float* __restrict__ log_sigma) {
    int idx = blockIdx.x * blockDim.x + threadIdx.x;
    if (idx == 0) g_invsig = expf(-log_sigma[0]);
    int p = idx & (Pn - 1);
    block_argmax_256(rp[idx], p, blockIdx.x);
}

// ---------------------------------------------------------------------------
// Kernel 3: mask step with fused seed-finalize prologue and fused next-step
// argmax partials. 4096 blocks x 256 threads; block = 256 consecutive pixels.
//   prologue: reduce this batch's 64 partials -> seed idx -> seed colour (smem)
//   k<Kn-1 : stage[k][idx] = log_m (streamed) ; logs update ; argmax partial
//   k=Kn-1 : read staged planes, write out [idx][11] contiguous
// ---------------------------------------------------------------------------
__global__ void step_kernel(float* __restrict__ out,
                            const float* __restrict__ rp,
                            int k, int first, int last) {
    __shared__ float s_seed[Cn];
    __shared__ float rsv[2];
    __shared__ int   rsp[2];

    int tid = threadIdx.x;
    int b   = blockIdx.x >> 6;                 // batch of this block

    // ---- fused per-batch argmax finalize + seed gather ----
    if (tid < 64) {
        float v = g_pval[b * PB + tid];
        int   p = g_pidx[b * PB + tid];
#pragma unroll
        for (int o = 16; o; o >>= 1) {
            float ov = __shfl_down_sync(0xFFFFFFFFu, v, o);
            int   op = __shfl_down_sync(0xFFFFFFFFu, p, o);
            if (ov > v || (ov == v && op < p)) { v = ov; p = op; }
        }
        if ((tid & 31) == 0) { rsv[tid >> 5] = v; rsp[tid >> 5] = p; }
    }
    __syncthreads();
    if (tid == 0) {
        int p = rsp[0];
        if (rsv[1] > rsv[0] || (rsv[1] == rsv[0] && rsp[1] < p)) p = rsp[1];
        rsp[0] = p;                            // broadcast winning index
    }
    __syncthreads();
    if (tid < Cn)
        s_seed[tid] = g_colour[((size_t)b * Cn + tid) * Pn + rsp[0]];
    __syncthreads();

    // ---- per-pixel step ----
    int idx = blockIdx.x * 256 + tid;          // 0 .. BP-1
    int p   = idx & (Pn - 1);

    float ls = first ? 0.0f : g_logs[idx];

    const float* cb = g_colour + (size_t)b * Cn * Pn + p;
    float d2 = 0.0f;
#pragma unroll
    for (int c = 0; c < Cn; c++) {
        float t = __ldg(cb + (size_t)c * Pn) - s_seed[c];
        d2 += t * t;
    }

    const float LOG2E = 1.4426950408889634f;
    const float L_LO  = -4.6051702f;      // log(0.01f)
    const float L_HI  = -0.010050326f;    // log(0.99f)

    float t = -(d2 * g_invsig);                    // ln-scale exponent
    float alpha = exp2f(t * LOG2E);
    alpha = fminf(fmaxf(alpha, 0.01f), 0.99f);
    float log_a = fminf(fmaxf(t, L_LO), L_HI);     // == log(clamped alpha)
    float log_m = ls + log_a;
    float ls_new = ls + logf(1.0f - alpha);

    if (!last) {
        __stcs(&g_stage[(size_t)k * BP + idx], log_m);   // stream: keep L2 clean
        g_logs[idx] = ls_new;
        float v = rp[idx] * expf(ls_new);
        block_argmax_256(v, p, blockIdx.x);
    } else {
        float* op = out + (size_t)idx * (Kn + 1);
#pragma unroll
        for (int j = 0; j < Kn - 1; j++)
            __stcs(&op[j], __ldcs(&g_stage[(size_t)j * BP + idx]));
        __stcs(&op[Kn - 1], log_m);
        __stcs(&op[Kn], ls_new);
    }
}

// ---------------------------------------------------------------------------
extern "C" void kernel_launch(void* const* d_in, const int* in_sizes, int n_in,
                              void* d_out, int out_size) {
    const float* features  = (const float*)d_in[0];
    const float* rand_pix  = (const float*)d_in[1];
    const float* conv_w    = (const float*)d_in[2];
    const float* conv_b    = (const float*)d_in[3];
    const float* gate      = (const float*)d_in[4];
    const float* log_sigma = (const float*)d_in[5];
    float* out = (float*)d_out;

    (void)in_sizes; (void)n_in; (void)out_size;

    conv_kernel<<<(BP / 4) / 256, 256>>>((const float4*)features,
                                         conv_w, conv_b, gate);
    init_partial_kernel<<<NBLK, 256>>>(rand_pix, log_sigma);

    for (int k = 0; k < Kn; k++)
        step_kernel<<<NBLK, 256>>>(out, rand_pix,
                                   k, k == 0 ? 1 : 0, k == Kn - 1 ? 1 : 0);
}

// round 7
// speedup vs baseline: 1.2394x; 1.1259x over previous
#include <cuda_runtime.h>
#include <cstdint>

#define Bn 64
#define Fn 64
#define Cn 8
#define Pn 16384              // pixels per image (128x128)
#define Kn 10                 // steps_to_run
#define BP (Bn * Pn)          // 1048576 total pixels

// Scratch (device globals: allocation-free per harness rules)
__device__ float g_colour[(size_t)Bn * Cn * Pn];  // [b][c][p]   33.5 MB
__device__ float g_stage[(size_t)(Kn - 1) * BP];  // [k][b*p]    37.7 MB (streamed)

// ---------------------------------------------------------------------------
__device__ __forceinline__ uint32_t smem_u32(const void* p) {
    uint32_t a;
    asm("{ .reg .u64 t; cvta.to.shared.u64 t, %1; cvt.u32.u64 %0, t; }"
        : "=r"(a) : "l"(p));
    return a;
}

// ---------------------------------------------------------------------------
// Kernel 1: 1x1 conv + gate + coordinate channels -> g_colour.
// ---------------------------------------------------------------------------
__global__ void conv_kernel(const float4* __restrict__ feat,
                            const float* __restrict__ w,
                            const float* __restrict__ bias,
                            const float* __restrict__ gate) {
    __shared__ float ws[Cn * Fn];
    __shared__ float bs[Cn];
    int tid = threadIdx.x;
    for (int i = tid; i < Cn * Fn; i += blockDim.x) ws[i] = w[i];
    if (tid < Cn) bs[tid] = bias[tid];
    __syncthreads();

    int gidx = blockIdx.x * blockDim.x + tid;   // 0 .. BP/4-1
    int b = gidx >> 12;
    int q = gidx & 4095;

    const float4* fb = feat + (size_t)b * (Fn * Pn / 4) + q;

    float4 acc[Cn];
#pragma unroll
    for (int c = 0; c < Cn; c++) {
        float bb = bs[c];
        acc[c] = make_float4(bb, bb, bb, bb);
    }

#pragma unroll 8
    for (int f = 0; f < Fn; f++) {
        float4 v = __ldcs(&fb[(size_t)f * (Pn / 4)]);   // stream features
#pragma unroll
        for (int c = 0; c < Cn; c++) {
            float wc = ws[c * Fn + f];
            acc[c].x += v.x * wc;
            acc[c].y += v.y * wc;
            acc[c].z += v.z * wc;
            acc[c].w += v.w * wc;
        }
    }

    float g = gate[0];
#pragma unroll
    for (int c = 0; c < Cn; c++) {
        acc[c].x *= g; acc[c].y *= g; acc[c].z *= g; acc[c].w *= g;
    }

    int p0 = q << 2;
    int h  = p0 >> 7;
    int wc0 = p0 & 127;
    const float step = 2.0f / 127.0f;
    float yy = -1.0f + step * (float)h;
    acc[6].x += yy; acc[6].y += yy; acc[6].z += yy; acc[6].w += yy;
    float xx = -1.0f + step * (float)wc0;
    acc[7].x += xx;
    acc[7].y += xx + step;
    acc[7].z += xx + 2.0f * step;
    acc[7].w += xx + 3.0f * step;

    float4* cb = (float4*)g_colour;
#pragma unroll
    for (int c = 0; c < Cn; c++)
        cb[((size_t)b * Cn + c) * (Pn / 4) + q] = acc[c];
}

// ---------------------------------------------------------------------------
// Kernel 2: persistent step loop. 128 CTAs x 512 thr, cluster(2): one batch
// per cluster, each CTA owns half the image (8192 px = 16 px/thread).
// Per step: CTA argmax reduce -> DSMEM exchange -> seed gather -> pixel loop.
// rp / log_s / last-step masks live in registers across all 10 steps.
// ---------------------------------------------------------------------------
__global__ void __launch_bounds__(512, 1) __cluster_dims__(2, 1, 1)
step_loop_kernel(float* __restrict__ out, const float4* __restrict__ rp4,
                 const float* __restrict__ log_sigma) {
    __shared__ float s_wv[16];
    __shared__ int   s_wp[16];
    __shared__ float s_slotv[2];
    __shared__ int   s_sloti[2];
    __shared__ int   s_pstar;
    __shared__ float s_seed[Cn];

    const int tid = threadIdx.x;
    const int b = blockIdx.x >> 1;              // batch
    const int h = blockIdx.x & 1;               // half of image
    uint32_t rank;
    asm("mov.u32 %0, %%cluster_ctarank;" : "=r"(rank));
    const uint32_t peer = rank ^ 1u;

    const float invsig = expf(-log_sigma[0]);
    const float LOG2E = 1.4426950408889634f;
    const float L_LO  = -4.6051702f;      // log(0.01f)
    const float L_HI  = -0.010050326f;    // log(0.99f)

    const int base4 = h * 2048 + tid;           // float4 index within batch plane
    const float4* colour4 = (const float4*)g_colour;
    float4* stage4 = (float4*)g_stage;

    float4 rp[4];
#pragma unroll
    for (int j = 0; j < 4; j++)
        rp[j] = __ldg(&rp4[b * 4096 + base4 + j * 512]);

    float ls[16];
#pragma unroll
    for (int i = 0; i < 16; i++) ls[i] = 0.0f;
    float lm9[16];

    // k=0 argmax candidate straight from rand_pixel (scope == 1)
    float vl = -3.402823466e38f; int pl = 0;
#pragma unroll
    for (int j = 0; j < 4; j++) {
        int pbase = h * 8192 + j * 2048 + (tid << 2);
        float vv[4] = {rp[j].x, rp[j].y, rp[j].z, rp[j].w};
#pragma unroll
        for (int i = 0; i < 4; i++)
            if (vv[i] > vl) { vl = vv[i]; pl = pbase + i; }   // ascending p: keep first
    }

    for (int k = 0; k < Kn; k++) {
        // ---- CTA argmax reduce of (vl, pl), first-index tie-break ----
#pragma unroll
        for (int o = 16; o; o >>= 1) {
            float ov = __shfl_down_sync(0xFFFFFFFFu, vl, o);
            int   op = __shfl_down_sync(0xFFFFFFFFu, pl, o);
            if (ov > vl || (ov == vl && op < pl)) { vl = ov; pl = op; }
        }
        if ((tid & 31) == 0) { s_wv[tid >> 5] = vl; s_wp[tid >> 5] = pl; }
        __syncthreads();
        if (tid < 32) {
            float v2 = (tid < 16) ? s_wv[tid] : -3.402823466e38f;
            int   p2 = (tid < 16) ? s_wp[tid] : 0x7FFFFFFF;
#pragma unroll
            for (int o = 8; o; o >>= 1) {
                float ov = __shfl_down_sync(0xFFFFFFFFu, v2, o);
                int   op = __shfl_down_sync(0xFFFFFFFFu, p2, o);
                if (ov > v2 || (ov == v2 && op < p2)) { v2 = ov; p2 = op; }
            }
            if (tid == 0) { s_slotv[k & 1] = v2; s_sloti[k & 1] = p2; }
        }
        __syncthreads();

        // ---- exchange CTA winners across the 2-CTA cluster ----
        asm volatile("barrier.cluster.arrive.aligned;" ::: "memory");
        asm volatile("barrier.cluster.wait.aligned;" ::: "memory");
        if (tid == 0) {
            int par = k & 1;
            uint32_t av = smem_u32(&s_slotv[par]);
            uint32_t ai = smem_u32(&s_sloti[par]);
            float pv; int pi;
            asm volatile("{ .reg .b32 r; mapa.shared::cluster.u32 r, %1, %2; "
                         "ld.shared::cluster.f32 %0, [r]; }"
                         : "=f"(pv) : "r"(av), "r"(peer));
            asm volatile("{ .reg .b32 r; mapa.shared::cluster.u32 r, %1, %2; "
                         "ld.shared::cluster.u32 %0, [r]; }"
                         : "=r"(pi) : "r"(ai), "r"(peer));
            float mv = s_slotv[par]; int mp = s_sloti[par];
            if (pv > mv || (pv == mv && pi < mp)) mp = pi;
            s_pstar = mp;
        }
        __syncthreads();
        if (tid < Cn)
            s_seed[tid] = g_colour[((size_t)b * Cn + tid) * Pn + s_pstar];
        __syncthreads();

        float seed[Cn];
#pragma unroll
        for (int c = 0; c < Cn; c++) seed[c] = s_seed[c];

        const int last = (k == Kn - 1);
        vl = -3.402823466e38f; pl = 0;

        // ---- pixel loop: 16 px/thread as 4 float4 groups ----
#pragma unroll
        for (int j = 0; j < 4; j++) {
            float4 col[Cn];
#pragma unroll
            for (int c = 0; c < Cn; c++)
                col[c] = colour4[((size_t)b * Cn + c) * 4096 + base4 + j * 512];

            float4 d2 = make_float4(0.f, 0.f, 0.f, 0.f);
#pragma unroll
            for (int c = 0; c < Cn; c++) {
                float sc = seed[c];
                float tx = col[c].x - sc; d2.x += tx * tx;
                float ty = col[c].y - sc; d2.y += ty * ty;
                float tz = col[c].z - sc; d2.z += tz * tz;
                float tw = col[c].w - sc; d2.w += tw * tw;
            }

            int pbase = h * 8192 + j * 2048 + (tid << 2);
            float dd[4] = {d2.x, d2.y, d2.z, d2.w};
            float rr[4] = {rp[j].x, rp[j].y, rp[j].z, rp[j].w};
            float lmv[4];
#pragma unroll
            for (int i = 0; i < 4; i++) {
                float t = -(dd[i] * invsig);
                float alpha = exp2f(t * LOG2E);
                alpha = fminf(fmaxf(alpha, 0.01f), 0.99f);
                float log_a = fminf(fmaxf(t, L_LO), L_HI);
                int li = j * 4 + i;
                float lsv = ls[li];
                lmv[i] = lsv + log_a;
                lsv += logf(1.0f - alpha);
                ls[li] = lsv;
                if (!last) {
                    float v = rr[i] * expf(lsv);
                    if (v > vl) { vl = v; pl = pbase + i; }   // ascending p
                } else {
                    lm9[li] = lmv[i];
                }
            }
            if (!last) {
                float4 lm4 = make_float4(lmv[0], lmv[1], lmv[2], lmv[3]);
                __stcs(&stage4[(size_t)k * (BP / 4) + b * 4096 + base4 + j * 512], lm4);
            }
        }
    }

    // ---- epilogue: assemble [b,p,11] output, contiguous 44B per pixel ----
#pragma unroll
    for (int j = 0; j < 4; j++) {
        int pbase = h * 8192 + j * 2048 + (tid << 2);
        float* op0 = out + ((size_t)b * Pn + pbase) * (Kn + 1);
        float* op1 = op0 + (Kn + 1);
        float* op2 = op1 + (Kn + 1);
        float* op3 = op2 + (Kn + 1);
#pragma unroll
        for (int kk = 0; kk < Kn - 1; kk++) {
            float4 s = __ldcs(&stage4[(size_t)kk * (BP / 4) + b * 4096 + base4 + j * 512]);
            __stcs(op0 + kk, s.x);
            __stcs(op1 + kk, s.y);
            __stcs(op2 + kk, s.z);
            __stcs(op3 + kk, s.w);
        }
        __stcs(op0 + Kn - 1, lm9[j * 4 + 0]); __stcs(op0 + Kn, ls[j * 4 + 0]);
        __stcs(op1 + Kn - 1, lm9[j * 4 + 1]); __stcs(op1 + Kn, ls[j * 4 + 1]);
        __stcs(op2 + Kn - 1, lm9[j * 4 + 2]); __stcs(op2 + Kn, ls[j * 4 + 2]);
        __stcs(op3 + Kn - 1, lm9[j * 4 + 3]); __stcs(op3 + Kn, ls[j * 4 + 3]);
    }
}

// ---------------------------------------------------------------------------
extern "C" void kernel_launch(void* const* d_in, const int* in_sizes, int n_in,
                              void* d_out, int out_size) {
    const float* features  = (const float*)d_in[0];
    const float* rand_pix  = (const float*)d_in[1];
    const float* conv_w    = (const float*)d_in[2];
    const float* conv_b    = (const float*)d_in[3];
    const float* gate      = (const float*)d_in[4];
    const float* log_sigma = (const float*)d_in[5];
    float* out = (float*)d_out;

    (void)in_sizes; (void)n_in; (void)out_size;

    conv_kernel<<<(BP / 4) / 256, 256>>>((const float4*)features,
                                         conv_w, conv_b, gate);
    step_loop_kernel<<<128, 512>>>(out, (const float4*)rand_pix, log_sigma);
}